// round 10
// baseline (speedup 1.0000x reference)
#include <cuda_runtime.h>
#include <cuda_bf16.h>
#include <cstdint>

#define N_NODES_MAX 100000
#define MASK_WORDS ((N_NODES_MAX + 31) / 32)
#define DSIGMA_DT (-0.0001f)
#define PHI_THRESH 0.3f
#define EPS 1e-8f

// Packed {pos.x, pos.y, pos.z, T} per node; accumulator {num.xyz, cnt};
// interface-mask bitmap (1 bit per node).
__device__ float4 g_packed[N_NODES_MAX];
__device__ float4 g_acc[N_NODES_MAX];
__device__ unsigned g_mask[MASK_WORDS];
__device__ int g_idx_is64;

// Per-node: pack {pos,T}, zero acc, build mask bitmap via ballot, detect dtype.
// (R8 version — proven fastest; prep is latency-floor bound, leave it alone.)
__global__ __launch_bounds__(256) void prep_kernel(
        const float* __restrict__ x,
        const float* __restrict__ pos,
        const unsigned int* __restrict__ ei_words,
        int n_nodes) {
    int i = blockIdx.x * blockDim.x + threadIdx.x;
    bool active = (i < n_nodes);

    unsigned bit = 0;
    if (active) {
        float p0 = __ldg(&pos[i * 3 + 0]);
        float p1 = __ldg(&pos[i * 3 + 1]);
        float p2 = __ldg(&pos[i * 3 + 2]);
        float t  = __ldg(&x[i * 9 + 3]);
        float phi = __ldg(&x[i * 9 + 8]);
        g_packed[i] = make_float4(p0, p1, p2, t);
        g_acc[i] = make_float4(0.f, 0.f, 0.f, 0.f);
        bit = (fabsf(phi) < PHI_THRESH) ? 1u : 0u;
    }
    unsigned word = __ballot_sync(0xFFFFFFFFu, bit);
    if ((threadIdx.x & 31) == 0 && i < n_nodes) {
        g_mask[i >> 5] = word;
    }

    if (i == 0) {
        // int64 little-endian with values < 2^31 => odd 32-bit words all zero.
        unsigned int acc = 0;
        #pragma unroll
        for (int k = 0; k < 64; k++) acc |= ei_words[2 * k + 1];
        g_idx_is64 = (acc == 0) ? 1 : 0;
    }
}

__device__ __forceinline__ void live_edge(int s, int d) {
    float4 a = __ldg(&g_packed[s]);
    float4 b = __ldg(&g_packed[d]);
    float dT = a.w - b.w;
    float px = a.x - b.x, py = a.y - b.y, pz = a.z - b.z;
    float w = dT / (px * px + py * py + pz * pz + EPS);
    float4* addr = &g_acc[d];
    asm volatile("red.global.add.v4.f32 [%0], {%1, %2, %3, %4};"
                 :: "l"(addr), "f"(w * px), "f"(w * py), "f"(w * pz), "f"(1.0f)
                 : "memory");
}

// Grid-stride edge scatter, 2-way unrolled with upfront batched index loads:
// both src+dst for both slots issued before any dependent work (src lines are
// warp-fetched with ~99.98% probability anyway -> zero extra bytes, double
// the load-level parallelism). Mask skips ~76% of gathers/REDs.
__global__ __launch_bounds__(512) void edge_scatter_kernel(
        const void* __restrict__ edge_index, int n_edges, int mask_words) {
    __shared__ unsigned smask[MASK_WORDS];
    for (int w = threadIdx.x; w < mask_words; w += blockDim.x)
        smask[w] = g_mask[w];
    __syncthreads();

    const int S = gridDim.x * blockDim.x;       // stride
    const int t0 = blockIdx.x * blockDim.x + threadIdx.x;
    const int is64 = g_idx_is64;

    if (is64) {
        const long long* ei = (const long long*)edge_index;
        int e = t0;
        for (; e + S < n_edges; e += 2 * S) {
            // 4 independent coalesced loads in flight.
            long long d0l = ei[n_edges + e];
            long long s0l = ei[e];
            long long d1l = ei[n_edges + e + S];
            long long s1l = ei[e + S];
            int d0 = (int)d0l, d1 = (int)d1l;
            if ((smask[d0 >> 5] >> (d0 & 31)) & 1u) live_edge((int)s0l, d0);
            if ((smask[d1 >> 5] >> (d1 & 31)) & 1u) live_edge((int)s1l, d1);
        }
        if (e < n_edges) {
            int d = (int)ei[n_edges + e];
            if ((smask[d >> 5] >> (d & 31)) & 1u) live_edge((int)ei[e], d);
        }
    } else {
        const int* ei = (const int*)edge_index;
        int e = t0;
        for (; e + S < n_edges; e += 2 * S) {
            int d0 = ei[n_edges + e];
            int s0 = ei[e];
            int d1 = ei[n_edges + e + S];
            int s1 = ei[e + S];
            if ((smask[d0 >> 5] >> (d0 & 31)) & 1u) live_edge(s0, d0);
            if ((smask[d1 >> 5] >> (d1 & 31)) & 1u) live_edge(s1, d1);
        }
        if (e < n_edges) {
            int d = ei[n_edges + e];
            if ((smask[d >> 5] >> (d & 31)) & 1u) live_edge(ei[e], d);
        }
    }
}

__global__ __launch_bounds__(256) void finalize_kernel(
        float* __restrict__ out, int n_nodes) {
    int i = blockIdx.x * blockDim.x + threadIdx.x;
    if (i >= n_nodes) return;

    unsigned bit = (g_mask[i >> 5] >> (i & 31)) & 1u;
    float4 a = g_acc[i];

    float cnt = fmaxf(a.w, 1.0f);
    float s = bit ? (DSIGMA_DT / cnt) : 0.0f;

    out[i * 3 + 0] = s * a.x;
    out[i * 3 + 1] = s * a.y;
    out[i * 3 + 2] = s * a.z;
}

extern "C" void kernel_launch(void* const* d_in, const int* in_sizes, int n_in,
                              void* d_out, int out_size) {
    const float* x = (const float*)d_in[0];    // [N, 9]
    const float* pos = (const float*)d_in[1];  // [N, 3]
    const void* edge_index = d_in[2];          // [2, E] int32 or int64

    int n_nodes = in_sizes[1] / 3;
    int n_edges = in_sizes[2] / 2;
    int mask_words = (n_nodes + 31) / 32;
    float* out = (float*)d_out;

    prep_kernel<<<(n_nodes + 255) / 256, 256>>>(
        x, pos, (const unsigned int*)edge_index, n_nodes);

    int eblocks = (n_edges + 1023) / 1024;      // 2 edges/thread nominal
    if (eblocks > 592) eblocks = 592;           // ~4 blocks/SM, grid-stride
    edge_scatter_kernel<<<eblocks, 512>>>(edge_index, n_edges, mask_words);

    finalize_kernel<<<(n_nodes + 255) / 256, 256>>>(out, n_nodes);
}

// round 11
// speedup vs baseline: 1.0125x; 1.0125x over previous
#include <cuda_runtime.h>
#include <cuda_bf16.h>
#include <cstdint>

#define N_NODES_MAX 100000
#define MASK_WORDS ((N_NODES_MAX + 31) / 32)
#define DSIGMA_DT (-0.0001f)
#define PHI_THRESH 0.3f
#define EPS 1e-8f

#define EDGE_BLOCKS 592          // 148 SMs x 4 blocks -> all co-resident
#define EDGE_TPB 512

// Packed {pos.x, pos.y, pos.z, T}; accumulator {num.xyz, cnt} (zero-init at
// module load, re-zeroed by finalize each execution); mask bitmap; flags.
__device__ float4 g_packed[N_NODES_MAX];
__device__ float4 g_acc[N_NODES_MAX];
__device__ unsigned g_mask[MASK_WORDS];
__device__ int g_idx_is64;
__device__ unsigned g_prep_done;   // reset to 0 by finalize each execution

__device__ __forceinline__ void live_edge(int s, int d) {
    float4 a = __ldg(&g_packed[s]);
    float4 b = __ldg(&g_packed[d]);
    float dT = a.w - b.w;
    float px = a.x - b.x, py = a.y - b.y, pz = a.z - b.z;
    float w = dT / (px * px + py * py + pz * pz + EPS);
    float4* addr = &g_acc[d];
    asm volatile("red.global.add.v4.f32 [%0], {%1, %2, %3, %4};"
                 :: "l"(addr), "f"(w * px), "f"(w * py), "f"(w * pz), "f"(1.0f)
                 : "memory");
}

// Fused prep + edge scatter. Blocks [0, n_prep_blocks) pack their 512-node
// slab and build the mask bitmap, then signal; all blocks wait on the flag,
// stage the bitmap in smem, and run the grid-stride edge loop (R8 body:
// __ldcs index stream, skip ~76% masked-out edges).
__global__ __launch_bounds__(EDGE_TPB) void prep_edge_kernel(
        const float* __restrict__ x,
        const float* __restrict__ pos,
        const void* __restrict__ edge_index,
        int n_nodes, int n_edges, int mask_words, int n_prep_blocks) {
    __shared__ unsigned smask[MASK_WORDS];
    const int tid = threadIdx.x;
    const int bid = blockIdx.x;

    // ── prep portion ──
    if (bid < n_prep_blocks) {
        int i = bid * EDGE_TPB + tid;
        unsigned bit = 0;
        if (i < n_nodes) {
            float p0 = __ldg(&pos[i * 3 + 0]);
            float p1 = __ldg(&pos[i * 3 + 1]);
            float p2 = __ldg(&pos[i * 3 + 2]);
            float t  = __ldg(&x[i * 9 + 3]);
            float phi = __ldg(&x[i * 9 + 8]);
            g_packed[i] = make_float4(p0, p1, p2, t);
            bit = (fabsf(phi) < PHI_THRESH) ? 1u : 0u;
        }
        unsigned word = __ballot_sync(0xFFFFFFFFu, bit);
        if ((tid & 31) == 0 && i < n_nodes) g_mask[i >> 5] = word;

        if (bid == 0 && tid == 0) {
            // int64 LE with values < 2^31 => odd 32-bit words all zero.
            const unsigned int* w = (const unsigned int*)edge_index;
            unsigned int acc = 0;
            #pragma unroll
            for (int k = 0; k < 64; k++) acc |= w[2 * k + 1];
            g_idx_is64 = (acc == 0) ? 1 : 0;
        }
        __syncthreads();
        if (tid == 0) {
            __threadfence();                    // publish slab before signal
            atomicAdd(&g_prep_done, 1u);
        }
    }

    // ── wait for all prep slabs ──
    if (tid == 0) {
        volatile unsigned* done = &g_prep_done;
        while (*done < (unsigned)n_prep_blocks) { __nanosleep(32); }
        __threadfence();                        // acquire
    }
    __syncthreads();

    // ── stage mask bitmap in smem ──
    for (int w = tid; w < mask_words; w += EDGE_TPB) smask[w] = g_mask[w];
    __syncthreads();

    // ── edge scatter (R8 body) ──
    const int S = gridDim.x * EDGE_TPB;
    const int start = bid * EDGE_TPB + tid;

    if (g_idx_is64) {
        const long long* ei = (const long long*)edge_index;
        for (int e = start; e < n_edges; e += S) {
            int d = (int)__ldcs(&ei[n_edges + e]);
            if ((smask[d >> 5] >> (d & 31)) & 1u) {
                int s = (int)__ldcs(&ei[e]);
                live_edge(s, d);
            }
        }
    } else {
        const int* ei = (const int*)edge_index;
        for (int e = start; e < n_edges; e += S) {
            int d = __ldcs(&ei[n_edges + e]);
            if ((smask[d >> 5] >> (d & 31)) & 1u) {
                int s = __ldcs(&ei[e]);
                live_edge(s, d);
            }
        }
    }
}

// Finalize + reset for next execution: write output, zero acc (only masked-in
// nodes ever accumulate), reset the prep-done flag.
__global__ __launch_bounds__(256) void finalize_kernel(
        float* __restrict__ out, int n_nodes) {
    int i = blockIdx.x * blockDim.x + threadIdx.x;
    if (i >= n_nodes) return;

    unsigned bit = (g_mask[i >> 5] >> (i & 31)) & 1u;
    float4 a = g_acc[i];

    float cnt = fmaxf(a.w, 1.0f);
    float s = bit ? (DSIGMA_DT / cnt) : 0.0f;

    out[i * 3 + 0] = s * a.x;
    out[i * 3 + 1] = s * a.y;
    out[i * 3 + 2] = s * a.z;

    if (bit) g_acc[i] = make_float4(0.f, 0.f, 0.f, 0.f);
    if (i == 0) g_prep_done = 0;
}

extern "C" void kernel_launch(void* const* d_in, const int* in_sizes, int n_in,
                              void* d_out, int out_size) {
    const float* x = (const float*)d_in[0];    // [N, 9]
    const float* pos = (const float*)d_in[1];  // [N, 3]
    const void* edge_index = d_in[2];          // [2, E] int32 or int64

    int n_nodes = in_sizes[1] / 3;
    int n_edges = in_sizes[2] / 2;
    int mask_words = (n_nodes + 31) / 32;
    int n_prep_blocks = (n_nodes + EDGE_TPB - 1) / EDGE_TPB;
    float* out = (float*)d_out;

    prep_edge_kernel<<<EDGE_BLOCKS, EDGE_TPB>>>(
        x, pos, edge_index, n_nodes, n_edges, mask_words, n_prep_blocks);

    finalize_kernel<<<(n_nodes + 255) / 256, 256>>>(out, n_nodes);
}